// round 9
// baseline (speedup 1.0000x reference)
#include <cuda_runtime.h>
#include <cstdint>
#include <climits>

#define B_IMG   32
#define N_PRED  25200
#define KTOP    1024
#define NBINS   4096
#define NCAND   2048
#define CONF_T  0.25f
#define IOU_T   0.45f
#define NTRI    528       // 32*33/2 upper-triangle 32x32 word-blocks
#define PAIR_CAP 16384    // pairs per image (expected ~600 for this data)

typedef unsigned long long ull;

// ---------------- scratch (static device globals; no allocation) ----------------
// g_hist / g_paircnt start zeroed (module load) and are re-zeroed by k4 at the
// end of every launch, so each kernel_launch call sees zeroed state.
__device__ float        g_scores[B_IMG * N_PRED];      // 3.2 MB
__device__ unsigned int g_hist[B_IMG * NBINS];         // 512 KB
__device__ float4       g_boxes[B_IMG * KTOP];
__device__ float        g_topsc[B_IMG * KTOP];
__device__ unsigned int g_paircnt[B_IMG];
__device__ unsigned int g_pairs[B_IMG * PAIR_CAP];     // 2 MB

__device__ __forceinline__ ull umin64(ull a, ull b) { return a < b ? a : b; }
__device__ __forceinline__ ull umax64(ull a, ull b) { return a > b ? a : b; }

// k4 smem: dense mask [word w][row i], column stride 257 uint4 (odd -> conflict-free)
#define K4_MASK_U4   (32 * 257)                 // 8224 uint4
#define K4_SMEM_B    (K4_MASK_U4 * 16)          // 131584 bytes

// ================= K1: scores + global per-image histogram (full-chip) =================
__global__ void __launch_bounds__(1024)
k1_score(const float* __restrict__ pred) {
    int b = blockIdx.y;
    int i = blockIdx.x * 1024 + threadIdx.x;
    if (i >= N_PRED) return;
    const float* p = pred + ((size_t)(b * N_PRED + i)) * 16;
    float obj = __ldg(p + 4);
    float cls = __ldg(p + 15);
    float sc  = __fmul_rn(cls, obj);
    bool valid = (obj > CONF_T) && (sc > CONF_T);
    g_scores[b * N_PRED + i] = valid ? sc : -1.0f;
    if (valid) {
        unsigned bin = (__float_as_uint(sc) - 0x3E800000u) >> 12;
        if (bin > NBINS - 1) bin = NBINS - 1;
        atomicAdd(&g_hist[b * NBINS + bin], 1u);
    }
}

// ================= K2: select + compact + sort + gather (per-image CTA) =================
__global__ void __launch_bounds__(1024, 1)
k2_topk(const float* __restrict__ pred, float* __restrict__ dout) {
    __shared__ ull s_cand[NCAND];    // 16 KB
    __shared__ int s_part[32];
    __shared__ int s_binB, s_cnt;

    int b   = blockIdx.x;
    int t   = threadIdx.x;
    int lane = t & 31, wid = t >> 5;

    if (t == 0) { s_binB = 0; s_cnt = 0; }

    // ---- reversed counts straight from global hist (built by k1) ----
    const unsigned* hb = &g_hist[b * NBINS];
    unsigned c0 = __ldg(hb + (NBINS - 1 - 4 * t));
    unsigned c1 = __ldg(hb + (NBINS - 1 - (4 * t + 1)));
    unsigned c2 = __ldg(hb + (NBINS - 1 - (4 * t + 2)));
    unsigned c3 = __ldg(hb + (NBINS - 1 - (4 * t + 3)));
    int v = (int)(c0 + c1 + c2 + c3);
    int x = v;
    #pragma unroll
    for (int off = 1; off < 32; off <<= 1) {
        int y = __shfl_up_sync(0xFFFFFFFFu, x, off);
        if (lane >= off) x += y;
    }
    if (lane == 31) s_part[wid] = x;
    __syncthreads();
    if (wid == 0) {
        int y = s_part[lane];
        #pragma unroll
        for (int off = 1; off < 32; off <<= 1) {
            int z = __shfl_up_sync(0xFFFFFFFFu, y, off);
            if (lane >= off) y += z;
        }
        s_part[lane] = y;
    }
    __syncthreads();
    int incl = x + (wid > 0 ? s_part[wid - 1] : 0);
    int excl = incl - v;
    if (incl >= KTOP && excl < KTOP) {
        int c = excl;
        unsigned cs[4] = { c0, c1, c2, c3 };
        int rstar = 4 * t + 3;
        #pragma unroll
        for (int q = 0; q < 4; q++) {
            c += (int)cs[q];
            if (c >= KTOP) { rstar = 4 * t + q; break; }
        }
        s_binB = (NBINS - 1) - rstar;
    }
    __syncthreads();
    int binB = s_binB;

    // ---- compact candidates (float4 loads from L2-resident g_scores) ----
    const float4* gs4 = (const float4*)&g_scores[b * N_PRED];
    const int N4 = N_PRED / 4;             // 6300
    for (int i = t; i < N4; i += 1024) {
        float4 s = gs4[i];
        float sv[4] = { s.x, s.y, s.z, s.w };
        #pragma unroll
        for (int c = 0; c < 4; c++) {
            if (sv[c] > 0.0f) {
                unsigned bits = __float_as_uint(sv[c]);
                unsigned bin  = (bits - 0x3E800000u) >> 12;
                if (bin > NBINS - 1) bin = NBINS - 1;
                if ((int)bin >= binB) {
                    unsigned desc = ~(bits | 0x80000000u);
                    ull key = ((ull)desc << 32) | (unsigned)(i * 4 + c);
                    int pos = atomicAdd(&s_cnt, 1);
                    if (pos < NCAND) s_cand[pos] = key;
                }
            }
        }
    }
    __syncthreads();
    int cnt = s_cnt; if (cnt > NCAND) cnt = NCAND;
    const ull PAD = ((ull)0xBF800000u << 32);
    for (int i0 = t; i0 < NCAND; i0 += 1024)
        if (i0 >= cnt) s_cand[i0] = PAD;
    __syncthreads();

    // ---- bitonic sort: registers + shfl; smem only for 32<=j<=512 ----
    ull e0 = s_cand[t];
    ull e1 = s_cand[t + 1024];
    for (int k = 2; k <= NCAND; k <<= 1) {
        bool dir0 = ((t & k) == 0);
        bool dir1 = (((t + 1024) & k) == 0);
        for (int j = k >> 1; j > 0; j >>= 1) {
            if (j == 1024) {
                ull lo = umin64(e0, e1), hi = umax64(e0, e1);
                e0 = lo; e1 = hi;
            } else if (j >= 32) {
                s_cand[t] = e0; s_cand[t + 1024] = e1;
                __syncthreads();
                ull f0 = s_cand[t ^ j];
                ull f1 = s_cand[(t ^ j) + 1024];
                bool lower = ((t & j) == 0);
                e0 = (lower == dir0) ? umin64(e0, f0) : umax64(e0, f0);
                e1 = (lower == dir1) ? umin64(e1, f1) : umax64(e1, f1);
                __syncthreads();
            } else {
                ull f0 = __shfl_xor_sync(0xFFFFFFFFu, e0, j);
                ull f1 = __shfl_xor_sync(0xFFFFFFFFu, e1, j);
                bool lower = ((t & j) == 0);
                e0 = (lower == dir0) ? umin64(e0, f0) : umax64(e0, f0);
                e1 = (lower == dir1) ? umin64(e1, f1) : umax64(e1, f1);
            }
        }
    }

    // ---- gather top-1024 (thread t holds sorted element t in e0) ----
    unsigned idx  = (unsigned)(e0 & 0xFFFFFFFFu);
    unsigned mono = ~((unsigned)(e0 >> 32));
    unsigned sbits = (mono & 0x80000000u) ? (mono & 0x7FFFFFFFu) : ~mono;
    float sc = __uint_as_float(sbits);

    const float* pb = pred + (size_t)b * N_PRED * 16;
    const float4* p4 = (const float4*)(pb + (size_t)idx * 16);
    float4 v0 = p4[0];
    float4 v1 = p4[1];
    float4 v2 = p4[2];
    float4 v3 = p4[3];

    float hw = __fmul_rn(v0.z, 0.5f), hh = __fmul_rn(v0.w, 0.5f);
    float x1 = __fsub_rn(v0.x, hw), y1 = __fsub_rn(v0.y, hh);
    float x2 = __fadd_rn(v0.x, hw), y2 = __fadd_rn(v0.y, hh);

    float4* o4 = (float4*)(dout + (((size_t)(b * KTOP)) + t) * 16);
    o4[0] = make_float4(x1, y1, x2, y2);
    o4[1] = make_float4(sc, v1.y, v1.z, v1.w);
    o4[2] = v2;
    o4[3] = make_float4(v3.x, v3.y, v3.z, 0.0f);

    g_boxes[b * KTOP + t] = make_float4(x1, y1, x2, y2);
    g_topsc[b * KTOP + t] = sc;
}

// ================= K3: suppression pairs, triangle-packed, FFMA screen =================
__global__ void __launch_bounds__(1024)
k3_mask() {
    __shared__ float4 sbox[KTOP];
    __shared__ float  staj[KTOP];   // 0.45 * area * (1 - 1e-5)
    int b = blockIdx.y;
    int t = threadIdx.x;

    float4 bx = g_boxes[b * KTOP + t];
    sbox[t] = bx;
    float area = __fmul_rn(__fsub_rn(bx.z, bx.x), __fsub_rn(bx.w, bx.y));
    staj[t] = 0.45f * area * 0.99999f;
    __syncthreads();

    int g = blockIdx.x * 32 + (t >> 5);
    if (g >= NTRI) return;

    // map g -> (rowblock r, wordblock w>=r)
    int u = NTRI - g;
    int n = (int)((__fsqrt_rn((float)(8 * u + 1)) - 1.0f) * 0.5f);
    while (n * (n + 1) / 2 < u) n++;
    while ((n - 1) * n / 2 >= u) n--;
    int r    = 32 - n;
    int base = NTRI - n * (n + 1) / 2;
    int w    = r + (g - base);

    int lane = t & 31;
    int i = r * 32 + lane;
    float4 bi = sbox[i];
    float  ai = __fmul_rn(__fsub_rn(bi.z, bi.x), __fsub_rn(bi.w, bi.y));
    float  tqi_lo = 0.45f * (__fadd_rn(ai, 1e-7f)) * 0.99999f;

    unsigned amb = 0;
    #pragma unroll
    for (int kk = 0; kk < 32; kk++) {
        int j = w * 32 + kk;
        float4 bj = sbox[j];
        float iw = fmaxf(__fsub_rn(fminf(bi.z, bj.z), fmaxf(bi.x, bj.x)), 0.0f);
        float ih = fmaxf(__fsub_rn(fminf(bi.w, bj.w), fmaxf(bi.y, bj.y)), 0.0f);
        float inter = __fmul_rn(iw, ih);
        // screen: 1.45*inter > 0.45*(ai+aj+eps), RHS shrunk by 1e-5 (superset of true cond)
        if (fmaf(inter, 1.45f, -tqi_lo) > staj[j]) amb |= 1u << kk;
    }
    if (w == r) amb &= (0xFFFFFFFEu << lane);   // strict upper triangle on diagonal

    // exact resolution (bit-exact vs reference's RN divide)
    unsigned sup = 0;
    while (amb) {
        int kk = __ffs(amb) - 1; amb &= amb - 1;
        int j = w * 32 + kk;
        float4 bj = sbox[j];
        float aj = __fmul_rn(__fsub_rn(bj.z, bj.x), __fsub_rn(bj.w, bj.y));
        float iw = fmaxf(__fsub_rn(fminf(bi.z, bj.z), fmaxf(bi.x, bj.x)), 0.0f);
        float ih = fmaxf(__fsub_rn(fminf(bi.w, bj.w), fmaxf(bi.y, bj.y)), 0.0f);
        float inter = __fmul_rn(iw, ih);
        float den = __fadd_rn(__fsub_rn(__fadd_rn(ai, aj), inter), 1e-7f);
        if (__fdiv_rn(inter, den) > IOU_T) sup |= 1u << kk;
    }

    // emit sparse pairs (i suppresses j), j = w*32 + bit
    int npairs = __popc(sup);
    if (npairs) {
        unsigned pos = atomicAdd(&g_paircnt[b], (unsigned)npairs);
        while (sup) {
            int kk = __ffs(sup) - 1; sup &= sup - 1;
            if (pos < PAIR_CAP)
                g_pairs[b * PAIR_CAP + pos] = ((unsigned)i << 16) | (unsigned)(w * 32 + kk);
            pos++;
        }
    }
}

// ================= K4: smem mask from pairs + sparse serial greedy + output =================
__global__ void __launch_bounds__(512, 1)
k4_reduce(float* __restrict__ dout, float* __restrict__ keepout, int writeKeep) {
    extern __shared__ unsigned sm[];          // [w][i], column stride 1028 words
    uint4* sm4 = (uint4*)sm;
    __shared__ unsigned s_vm[32], s_keep[32];

    int b   = blockIdx.x;
    int tid = threadIdx.x;      // 0..511

    // ---- zero the mask region (8224 uint4 = 128.5 KB) ----
    for (int v = tid; v < K4_MASK_U4; v += 512)
        sm4[v] = make_uint4(0, 0, 0, 0);

    // ---- vmask ballots ----
    #pragma unroll
    for (int it = 0; it < 2; it++) {
        int row = it * 512 + tid;
        float scv = g_topsc[b * KTOP + row];
        unsigned bal = __ballot_sync(0xFFFFFFFFu, scv > 0.0f);
        if ((tid & 31) == 0) s_vm[row >> 5] = bal;
    }
    __syncthreads();

    // ---- scatter sparse pairs into the smem mask ----
    unsigned pcnt = g_paircnt[b];
    if (pcnt > PAIR_CAP) pcnt = PAIR_CAP;
    for (unsigned p = tid; p < pcnt; p += 512) {
        unsigned pr = g_pairs[b * PAIR_CAP + p];
        unsigned i = pr >> 16;
        unsigned j = pr & 0xFFFFu;
        atomicOr(&sm[(j >> 5) * 1028 + i], 1u << (j & 31));
    }

    // ---- re-zero per-image counters for the NEXT kernel_launch call ----
    {
        uint4* hz = (uint4*)&g_hist[b * NBINS];   // 1024 uint4
        hz[tid]       = make_uint4(0, 0, 0, 0);
        hz[tid + 512] = make_uint4(0, 0, 0, 0);
        if (tid == 0) g_paircnt[b] = 0;
    }
    __syncthreads();

    // ---- serial greedy (warp 0 only), smem-resident mask ----
    if (tid < 32) {
        int l = tid;
        unsigned removed = ~s_vm[l];
        const uint4* mrow = sm4 + l * 257;        // column l, rows as uint4

        unsigned d = sm[0 * 1028 + 0 * 32 + l];   // diag word, block 0
        uint4 c0 = mrow[0], c1 = mrow[1], c2 = mrow[2], c3 = mrow[3];
        uint4 c4 = mrow[4], c5 = mrow[5], c6 = mrow[6], c7 = mrow[7];

        for (int bi = 0; bi < 32; bi++) {
            unsigned dn = 0;
            uint4 n0, n1, n2, n3, n4, n5, n6, n7;
            n0 = n1 = n2 = n3 = n4 = n5 = n6 = n7 = make_uint4(0, 0, 0, 0);
            if (bi < 31) {
                dn = sm[(bi + 1) * 1028 + (bi + 1) * 32 + l];
                const uint4* nb = mrow + (bi + 1) * 8;
                n0 = nb[0]; n1 = nb[1]; n2 = nb[2]; n3 = nb[3];
                n4 = nb[4]; n5 = nb[5]; n6 = nb[6]; n7 = nb[7];
            }

            unsigned r = __shfl_sync(0xFFFFFFFFu, removed, bi);
            unsigned todo = __ballot_sync(0xFFFFFFFFu, d != 0u);
            while (todo) {
                int k = __ffs(todo) - 1; todo &= todo - 1;
                unsigned dk = __shfl_sync(0xFFFFFFFFu, d, k);
                if (!((r >> k) & 1u)) r |= dk;
            }
            unsigned keepw = ~r;

            unsigned mv[32] = { c0.x, c0.y, c0.z, c0.w, c1.x, c1.y, c1.z, c1.w,
                                c2.x, c2.y, c2.z, c2.w, c3.x, c3.y, c3.z, c3.w,
                                c4.x, c4.y, c4.z, c4.w, c5.x, c5.y, c5.z, c5.w,
                                c6.x, c6.y, c6.z, c6.w, c7.x, c7.y, c7.z, c7.w };
            unsigned a0 = 0, a1 = 0, a2 = 0, a3 = 0;
            #pragma unroll
            for (int k = 0; k < 32; k += 4) {
                a0 |= mv[k]     & (unsigned)((int)(keepw << (31 - k))       >> 31);
                a1 |= mv[k + 1] & (unsigned)((int)(keepw << (31 - (k + 1))) >> 31);
                a2 |= mv[k + 2] & (unsigned)((int)(keepw << (31 - (k + 2))) >> 31);
                a3 |= mv[k + 3] & (unsigned)((int)(keepw << (31 - (k + 3))) >> 31);
            }
            removed |= (a0 | a1) | (a2 | a3);

            d = dn;
            c0 = n0; c1 = n1; c2 = n2; c3 = n3;
            c4 = n4; c5 = n5; c6 = n6; c7 = n7;
        }
        s_keep[l] = ~removed;
    }
    __syncthreads();

    // ---- masked output: 512 threads x 2 rows ----
    #pragma unroll
    for (int it = 0; it < 2; it++) {
        int row = it * 512 + tid;
        unsigned keepbit = (s_keep[row >> 5] >> (row & 31)) & 1u;
        float* o = dout + ((size_t)b * KTOP + row) * 16;
        if (!keepbit) {
            float4 z = make_float4(0.f, 0.f, 0.f, 0.f);
            ((float4*)o)[0] = z; ((float4*)o)[1] = z;
            ((float4*)o)[2] = z; ((float4*)o)[3] = z;
        }
        if (writeKeep) keepout[b * KTOP + row] = keepbit ? 1.0f : 0.0f;
    }
}

// ---------------- launch ----------------
extern "C" void kernel_launch(void* const* d_in, const int* in_sizes, int n_in,
                              void* d_out, int out_size) {
    const float* pred = (const float*)d_in[0];
    float* out = (float*)d_out;
    const int DET = B_IMG * KTOP * 16;
    int writeKeep = (out_size >= DET + B_IMG * KTOP) ? 1 : 0;
    float* keepout = out + DET;

    static int attr_done = 0;
    if (!attr_done) {
        cudaFuncSetAttribute((const void*)k4_reduce,
                             cudaFuncAttributeMaxDynamicSharedMemorySize, K4_SMEM_B);
        attr_done = 1;
    }

    k1_score<<<dim3(25, B_IMG), 1024>>>(pred);
    k2_topk<<<B_IMG, 1024>>>(pred, out);
    k3_mask<<<dim3(17, B_IMG), 1024>>>();
    k4_reduce<<<B_IMG, 512, K4_SMEM_B>>>(out, keepout, writeKeep);
}

// round 12
// speedup vs baseline: 1.0332x; 1.0332x over previous
#include <cuda_runtime.h>
#include <cstdint>
#include <climits>

#define B_IMG   32
#define N_PRED  25200
#define KTOP    1024
#define NBINS   4096
#define NCAND   2048
#define CONF_T  0.25f
#define IOU_T   0.45f
#define NTRI    528       // 32*33/2 upper-triangle 32x32 word-blocks
#define PAIR_CAP 16384    // pairs per image (expected ~600 for this data)

typedef unsigned long long ull;

// ---------------- scratch (static device globals; no allocation) ----------------
// g_hist / g_paircnt start zeroed (module load) and are re-zeroed by k4 at the
// end of every launch, so each kernel_launch call sees zeroed state.
__device__ float        g_scores[B_IMG * N_PRED];      // 3.2 MB
__device__ unsigned int g_hist[B_IMG * NBINS];         // 512 KB
__device__ float4       g_boxes[B_IMG * KTOP];
__device__ float        g_topsc[B_IMG * KTOP];
__device__ unsigned int g_paircnt[B_IMG];
__device__ unsigned int g_pairs[B_IMG * PAIR_CAP];     // 2 MB

__device__ __forceinline__ ull umin64(ull a, ull b) { return a < b ? a : b; }
__device__ __forceinline__ ull umax64(ull a, ull b) { return a > b ? a : b; }

// ================= K1: scores + global per-image histogram (full-chip) =================
__global__ void __launch_bounds__(1024)
k1_score(const float* __restrict__ pred) {
    int b = blockIdx.y;
    int i = blockIdx.x * 1024 + threadIdx.x;
    if (i >= N_PRED) return;
    const float* p = pred + ((size_t)(b * N_PRED + i)) * 16;
    float obj = __ldg(p + 4);
    float cls = __ldg(p + 15);
    float sc  = __fmul_rn(cls, obj);
    bool valid = (obj > CONF_T) && (sc > CONF_T);
    g_scores[b * N_PRED + i] = valid ? sc : -1.0f;
    if (valid) {
        unsigned bin = (__float_as_uint(sc) - 0x3E800000u) >> 12;
        if (bin > NBINS - 1) bin = NBINS - 1;
        atomicAdd(&g_hist[b * NBINS + bin], 1u);
    }
}

// ================= K2: select + compact + sort + gather (per-image CTA) =================
__global__ void __launch_bounds__(1024, 1)
k2_topk(const float* __restrict__ pred, float* __restrict__ dout) {
    __shared__ ull s_cand[NCAND];    // 16 KB
    __shared__ int s_part[32];
    __shared__ int s_binB, s_cnt;

    int b   = blockIdx.x;
    int t   = threadIdx.x;
    int lane = t & 31, wid = t >> 5;

    if (t == 0) { s_binB = 0; s_cnt = 0; }

    // ---- reversed counts straight from global hist (built by k1) ----
    const unsigned* hb = &g_hist[b * NBINS];
    unsigned c0 = __ldg(hb + (NBINS - 1 - 4 * t));
    unsigned c1 = __ldg(hb + (NBINS - 1 - (4 * t + 1)));
    unsigned c2 = __ldg(hb + (NBINS - 1 - (4 * t + 2)));
    unsigned c3 = __ldg(hb + (NBINS - 1 - (4 * t + 3)));
    int v = (int)(c0 + c1 + c2 + c3);
    int x = v;
    #pragma unroll
    for (int off = 1; off < 32; off <<= 1) {
        int y = __shfl_up_sync(0xFFFFFFFFu, x, off);
        if (lane >= off) x += y;
    }
    if (lane == 31) s_part[wid] = x;
    __syncthreads();
    if (wid == 0) {
        int y = s_part[lane];
        #pragma unroll
        for (int off = 1; off < 32; off <<= 1) {
            int z = __shfl_up_sync(0xFFFFFFFFu, y, off);
            if (lane >= off) y += z;
        }
        s_part[lane] = y;
    }
    __syncthreads();
    int incl = x + (wid > 0 ? s_part[wid - 1] : 0);
    int excl = incl - v;
    if (incl >= KTOP && excl < KTOP) {
        int c = excl;
        unsigned cs[4] = { c0, c1, c2, c3 };
        int rstar = 4 * t + 3;
        #pragma unroll
        for (int q = 0; q < 4; q++) {
            c += (int)cs[q];
            if (c >= KTOP) { rstar = 4 * t + q; break; }
        }
        s_binB = (NBINS - 1) - rstar;
    }
    __syncthreads();
    int binB = s_binB;

    // ---- compact candidates (float4 loads from L2-resident g_scores) ----
    const float4* gs4 = (const float4*)&g_scores[b * N_PRED];
    const int N4 = N_PRED / 4;             // 6300
    for (int i = t; i < N4; i += 1024) {
        float4 s = gs4[i];
        float sv[4] = { s.x, s.y, s.z, s.w };
        #pragma unroll
        for (int c = 0; c < 4; c++) {
            if (sv[c] > 0.0f) {
                unsigned bits = __float_as_uint(sv[c]);
                unsigned bin  = (bits - 0x3E800000u) >> 12;
                if (bin > NBINS - 1) bin = NBINS - 1;
                if ((int)bin >= binB) {
                    unsigned desc = ~(bits | 0x80000000u);
                    ull key = ((ull)desc << 32) | (unsigned)(i * 4 + c);
                    int pos = atomicAdd(&s_cnt, 1);
                    if (pos < NCAND) s_cand[pos] = key;
                }
            }
        }
    }
    __syncthreads();
    int cnt = s_cnt; if (cnt > NCAND) cnt = NCAND;
    const ull PAD = ((ull)0xBF800000u << 32);
    for (int i0 = t; i0 < NCAND; i0 += 1024)
        if (i0 >= cnt) s_cand[i0] = PAD;
    __syncthreads();

    // ---- bitonic sort: registers + shfl; smem only for 32<=j<=512 ----
    ull e0 = s_cand[t];
    ull e1 = s_cand[t + 1024];
    for (int k = 2; k <= NCAND; k <<= 1) {
        bool dir0 = ((t & k) == 0);
        bool dir1 = (((t + 1024) & k) == 0);
        for (int j = k >> 1; j > 0; j >>= 1) {
            if (j == 1024) {
                ull lo = umin64(e0, e1), hi = umax64(e0, e1);
                e0 = lo; e1 = hi;
            } else if (j >= 32) {
                s_cand[t] = e0; s_cand[t + 1024] = e1;
                __syncthreads();
                ull f0 = s_cand[t ^ j];
                ull f1 = s_cand[(t ^ j) + 1024];
                bool lower = ((t & j) == 0);
                e0 = (lower == dir0) ? umin64(e0, f0) : umax64(e0, f0);
                e1 = (lower == dir1) ? umin64(e1, f1) : umax64(e1, f1);
                __syncthreads();
            } else {
                ull f0 = __shfl_xor_sync(0xFFFFFFFFu, e0, j);
                ull f1 = __shfl_xor_sync(0xFFFFFFFFu, e1, j);
                bool lower = ((t & j) == 0);
                e0 = (lower == dir0) ? umin64(e0, f0) : umax64(e0, f0);
                e1 = (lower == dir1) ? umin64(e1, f1) : umax64(e1, f1);
            }
        }
    }

    // ---- gather top-1024 (thread t holds sorted element t in e0) ----
    unsigned idx  = (unsigned)(e0 & 0xFFFFFFFFu);
    unsigned mono = ~((unsigned)(e0 >> 32));
    unsigned sbits = (mono & 0x80000000u) ? (mono & 0x7FFFFFFFu) : ~mono;
    float sc = __uint_as_float(sbits);

    const float* pb = pred + (size_t)b * N_PRED * 16;
    const float4* p4 = (const float4*)(pb + (size_t)idx * 16);
    float4 v0 = p4[0];
    float4 v1 = p4[1];
    float4 v2 = p4[2];
    float4 v3 = p4[3];

    float hw = __fmul_rn(v0.z, 0.5f), hh = __fmul_rn(v0.w, 0.5f);
    float x1 = __fsub_rn(v0.x, hw), y1 = __fsub_rn(v0.y, hh);
    float x2 = __fadd_rn(v0.x, hw), y2 = __fadd_rn(v0.y, hh);

    float4* o4 = (float4*)(dout + (((size_t)(b * KTOP)) + t) * 16);
    o4[0] = make_float4(x1, y1, x2, y2);
    o4[1] = make_float4(sc, v1.y, v1.z, v1.w);
    o4[2] = v2;
    o4[3] = make_float4(v3.x, v3.y, v3.z, 0.0f);

    g_boxes[b * KTOP + t] = make_float4(x1, y1, x2, y2);
    g_topsc[b * KTOP + t] = sc;
}

// ================= K3: suppression pairs, triangle-packed, FFMA screen =================
__global__ void __launch_bounds__(1024)
k3_mask() {
    __shared__ float4 sbox[KTOP];
    __shared__ float  staj[KTOP];   // 0.45 * area * (1 - 1e-5)
    int b = blockIdx.y;
    int t = threadIdx.x;

    float4 bx = g_boxes[b * KTOP + t];
    sbox[t] = bx;
    float area = __fmul_rn(__fsub_rn(bx.z, bx.x), __fsub_rn(bx.w, bx.y));
    staj[t] = 0.45f * area * 0.99999f;
    __syncthreads();

    int g = blockIdx.x * 32 + (t >> 5);
    if (g >= NTRI) return;

    // map g -> (rowblock r, wordblock w>=r)
    int u = NTRI - g;
    int n = (int)((__fsqrt_rn((float)(8 * u + 1)) - 1.0f) * 0.5f);
    while (n * (n + 1) / 2 < u) n++;
    while ((n - 1) * n / 2 >= u) n--;
    int r    = 32 - n;
    int base = NTRI - n * (n + 1) / 2;
    int w    = r + (g - base);

    int lane = t & 31;
    int i = r * 32 + lane;
    float4 bi = sbox[i];
    float  ai = __fmul_rn(__fsub_rn(bi.z, bi.x), __fsub_rn(bi.w, bi.y));
    float  tqi_lo = 0.45f * (__fadd_rn(ai, 1e-7f)) * 0.99999f;

    unsigned amb = 0;
    #pragma unroll
    for (int kk = 0; kk < 32; kk++) {
        int j = w * 32 + kk;
        float4 bj = sbox[j];
        float iw = fmaxf(__fsub_rn(fminf(bi.z, bj.z), fmaxf(bi.x, bj.x)), 0.0f);
        float ih = fmaxf(__fsub_rn(fminf(bi.w, bj.w), fmaxf(bi.y, bj.y)), 0.0f);
        float inter = __fmul_rn(iw, ih);
        // screen: 1.45*inter > 0.45*(ai+aj+eps), RHS shrunk by 1e-5 (superset of true cond)
        if (fmaf(inter, 1.45f, -tqi_lo) > staj[j]) amb |= 1u << kk;
    }
    if (w == r) amb &= (0xFFFFFFFEu << lane);   // strict upper triangle on diagonal

    // exact resolution (bit-exact vs reference's RN divide)
    unsigned sup = 0;
    while (amb) {
        int kk = __ffs(amb) - 1; amb &= amb - 1;
        int j = w * 32 + kk;
        float4 bj = sbox[j];
        float aj = __fmul_rn(__fsub_rn(bj.z, bj.x), __fsub_rn(bj.w, bj.y));
        float iw = fmaxf(__fsub_rn(fminf(bi.z, bj.z), fmaxf(bi.x, bj.x)), 0.0f);
        float ih = fmaxf(__fsub_rn(fminf(bi.w, bj.w), fmaxf(bi.y, bj.y)), 0.0f);
        float inter = __fmul_rn(iw, ih);
        float den = __fadd_rn(__fsub_rn(__fadd_rn(ai, aj), inter), 1e-7f);
        if (__fdiv_rn(inter, den) > IOU_T) sup |= 1u << kk;
    }

    // emit sparse pairs (i suppresses j), j = w*32 + bit; all pairs have i < j
    int npairs = __popc(sup);
    if (npairs) {
        unsigned pos = atomicAdd(&g_paircnt[b], (unsigned)npairs);
        while (sup) {
            int kk = __ffs(sup) - 1; sup &= sup - 1;
            if (pos < PAIR_CAP)
                g_pairs[b * PAIR_CAP + pos] = ((unsigned)i << 16) | (unsigned)(w * 32 + kk);
            pos++;
        }
    }
}

// ================= K4: parallel Jacobi fixpoint on sparse pairs + output =================
// keep[j] = valid[j] & ~OR_{(i,j) in P} keep[i]   (all pairs i<j)
// Unique fixpoint == sequential greedy result; converges in <= depth+1 iterations
// (nodes of dependency depth <= t are frozen at their greedy value after iter t+1).
__global__ void __launch_bounds__(512)
k4_reduce(float* __restrict__ dout, float* __restrict__ keepout, int writeKeep) {
    __shared__ unsigned s_valid[32], s_keep[32], s_removed[32];
    __shared__ unsigned s_pcnt;
    __shared__ int s_changed;

    int b   = blockIdx.x;
    int tid = threadIdx.x;      // 0..511

    // ---- vmask ballots ----
    #pragma unroll
    for (int it = 0; it < 2; it++) {
        int row = it * 512 + tid;
        float scv = g_topsc[b * KTOP + row];
        unsigned bal = __ballot_sync(0xFFFFFFFFu, scv > 0.0f);
        if ((tid & 31) == 0) s_valid[row >> 5] = bal;
    }

    // ---- re-zero per-image counters for the NEXT kernel_launch call ----
    {
        uint4* hz = (uint4*)&g_hist[b * NBINS];   // 1024 uint4
        hz[tid]       = make_uint4(0, 0, 0, 0);
        hz[tid + 512] = make_uint4(0, 0, 0, 0);
    }
    // tid 0 alone reads-then-zeros g_paircnt (program-ordered within one thread),
    // publishes via shared. NO other thread touches the global word -> no race.
    if (tid == 0) {
        unsigned pc = g_paircnt[b];
        g_paircnt[b] = 0;
        s_pcnt = pc;
    }
    __syncthreads();
    unsigned pcnt = s_pcnt;
    if (pcnt > PAIR_CAP) pcnt = PAIR_CAP;

    if (tid < 32) s_keep[tid] = s_valid[tid];
    __syncthreads();

    const unsigned* pl = &g_pairs[b * PAIR_CAP];
    for (;;) {
        if (tid < 32) s_removed[tid] = 0u;
        if (tid == 0) s_changed = 0;
        __syncthreads();

        for (unsigned p = tid; p < pcnt; p += 512) {
            unsigned pr = pl[p];
            unsigned i = pr >> 16;
            unsigned j = pr & 0xFFFFu;
            if ((s_keep[i >> 5] >> (i & 31)) & 1u)
                atomicOr(&s_removed[j >> 5], 1u << (j & 31));
        }
        __syncthreads();

        if (tid < 32) {
            unsigned nk = s_valid[tid] & ~s_removed[tid];
            if (nk != s_keep[tid]) { s_keep[tid] = nk; s_changed = 1; }
        }
        __syncthreads();
        int ch = s_changed;        // snapshot BEFORE anyone can overwrite it
        __syncthreads();           // all reads complete before next iter's writes
        if (!ch) break;
    }

    // ---- masked output: 512 threads x 2 rows ----
    #pragma unroll
    for (int it = 0; it < 2; it++) {
        int row = it * 512 + tid;
        unsigned keepbit = (s_keep[row >> 5] >> (row & 31)) & 1u;
        float* o = dout + ((size_t)b * KTOP + row) * 16;
        if (!keepbit) {
            float4 z = make_float4(0.f, 0.f, 0.f, 0.f);
            ((float4*)o)[0] = z; ((float4*)o)[1] = z;
            ((float4*)o)[2] = z; ((float4*)o)[3] = z;
        }
        if (writeKeep) keepout[b * KTOP + row] = keepbit ? 1.0f : 0.0f;
    }
}

// ---------------- launch ----------------
extern "C" void kernel_launch(void* const* d_in, const int* in_sizes, int n_in,
                              void* d_out, int out_size) {
    const float* pred = (const float*)d_in[0];
    float* out = (float*)d_out;
    const int DET = B_IMG * KTOP * 16;
    int writeKeep = (out_size >= DET + B_IMG * KTOP) ? 1 : 0;
    float* keepout = out + DET;

    k1_score<<<dim3(25, B_IMG), 1024>>>(pred);
    k2_topk<<<B_IMG, 1024>>>(pred, out);
    k3_mask<<<dim3(17, B_IMG), 1024>>>();
    k4_reduce<<<B_IMG, 512>>>(out, keepout, writeKeep);
}

// round 13
// speedup vs baseline: 1.0338x; 1.0006x over previous
#include <cuda_runtime.h>
#include <cstdint>
#include <climits>

#define B_IMG   32
#define N_PRED  25200
#define KTOP    1024
#define NBINS   4096
#define NCAND   2048
#define CONF_T  0.25f
#define IOU_T   0.45f
#define NTRI    528       // 32*33/2 upper-triangle 32x32 word-blocks
#define PAIR_CAP 16384    // pairs per image (expected ~600 for this data)
#define SMEM_PAIRS 6144   // staged pairs in k4 smem (24 KB)

typedef unsigned long long ull;

// ---------------- scratch (static device globals; no allocation) ----------------
// g_hist / g_paircnt start zeroed (module load) and are re-zeroed by k4 at the
// end of every launch, so each kernel_launch call sees zeroed state.
__device__ float        g_scores[B_IMG * N_PRED];      // 3.2 MB
__device__ unsigned int g_hist[B_IMG * NBINS];         // 512 KB
__device__ float4       g_boxes[B_IMG * KTOP];
__device__ float        g_topsc[B_IMG * KTOP];
__device__ unsigned int g_paircnt[B_IMG];
__device__ unsigned int g_pairs[B_IMG * PAIR_CAP];     // 2 MB

__device__ __forceinline__ ull umin64(ull a, ull b) { return a < b ? a : b; }
__device__ __forceinline__ ull umax64(ull a, ull b) { return a > b ? a : b; }

// ================= K1: scores + global per-image histogram (full-chip) =================
__global__ void __launch_bounds__(1024)
k1_score(const float* __restrict__ pred) {
    int b = blockIdx.y;
    int i = blockIdx.x * 1024 + threadIdx.x;
    if (i >= N_PRED) return;
    const float* p = pred + ((size_t)(b * N_PRED + i)) * 16;
    float obj = __ldg(p + 4);
    float cls = __ldg(p + 15);
    float sc  = __fmul_rn(cls, obj);
    bool valid = (obj > CONF_T) && (sc > CONF_T);
    g_scores[b * N_PRED + i] = valid ? sc : -1.0f;
    if (valid) {
        unsigned bin = (__float_as_uint(sc) - 0x3E800000u) >> 12;
        if (bin > NBINS - 1) bin = NBINS - 1;
        atomicAdd(&g_hist[b * NBINS + bin], 1u);
    }
}

// ================= K2: select + compact + sort + gather (per-image CTA) =================
__global__ void __launch_bounds__(1024, 1)
k2_topk(const float* __restrict__ pred, float* __restrict__ dout) {
    __shared__ ull s_cand[NCAND];    // 16 KB
    __shared__ int s_part[32];
    __shared__ int s_binB, s_cnt;

    int b   = blockIdx.x;
    int t   = threadIdx.x;
    int lane = t & 31, wid = t >> 5;

    if (t == 0) { s_binB = 0; s_cnt = 0; }

    // ---- reversed counts from global hist: one uint4 per thread ----
    // element index NBINS-4-4t..NBINS-1-4t -> x..w; reversed bin order:
    const uint4* hb4 = (const uint4*)&g_hist[b * NBINS];
    uint4 hv = __ldg(&hb4[(NBINS / 4 - 1) - t]);
    unsigned c0 = hv.w;   // hb[NBINS-1-4t]
    unsigned c1 = hv.z;   // hb[NBINS-2-4t]
    unsigned c2 = hv.y;   // hb[NBINS-3-4t]
    unsigned c3 = hv.x;   // hb[NBINS-4-4t]
    int v = (int)(c0 + c1 + c2 + c3);
    int x = v;
    #pragma unroll
    for (int off = 1; off < 32; off <<= 1) {
        int y = __shfl_up_sync(0xFFFFFFFFu, x, off);
        if (lane >= off) x += y;
    }
    if (lane == 31) s_part[wid] = x;
    __syncthreads();
    if (wid == 0) {
        int y = s_part[lane];
        #pragma unroll
        for (int off = 1; off < 32; off <<= 1) {
            int z = __shfl_up_sync(0xFFFFFFFFu, y, off);
            if (lane >= off) y += z;
        }
        s_part[lane] = y;
    }
    __syncthreads();
    int incl = x + (wid > 0 ? s_part[wid - 1] : 0);
    int excl = incl - v;
    if (incl >= KTOP && excl < KTOP) {
        int c = excl;
        unsigned cs[4] = { c0, c1, c2, c3 };
        int rstar = 4 * t + 3;
        #pragma unroll
        for (int q = 0; q < 4; q++) {
            c += (int)cs[q];
            if (c >= KTOP) { rstar = 4 * t + q; break; }
        }
        s_binB = (NBINS - 1) - rstar;
    }
    __syncthreads();
    int binB = s_binB;

    // ---- compact candidates (float4 loads from L2-resident g_scores) ----
    const float4* gs4 = (const float4*)&g_scores[b * N_PRED];
    const int N4 = N_PRED / 4;             // 6300
    for (int i = t; i < N4; i += 1024) {
        float4 s = gs4[i];
        float sv[4] = { s.x, s.y, s.z, s.w };
        #pragma unroll
        for (int c = 0; c < 4; c++) {
            if (sv[c] > 0.0f) {
                unsigned bits = __float_as_uint(sv[c]);
                unsigned bin  = (bits - 0x3E800000u) >> 12;
                if (bin > NBINS - 1) bin = NBINS - 1;
                if ((int)bin >= binB) {
                    unsigned desc = ~(bits | 0x80000000u);
                    ull key = ((ull)desc << 32) | (unsigned)(i * 4 + c);
                    int pos = atomicAdd(&s_cnt, 1);
                    if (pos < NCAND) s_cand[pos] = key;
                }
            }
        }
    }
    __syncthreads();
    int cnt = s_cnt; if (cnt > NCAND) cnt = NCAND;
    const ull PAD = ((ull)0xBF800000u << 32);
    for (int i0 = t; i0 < NCAND; i0 += 1024)
        if (i0 >= cnt) s_cand[i0] = PAD;
    __syncthreads();

    // ---- bitonic sort: registers + shfl; smem only for 32<=j<=512 ----
    ull e0 = s_cand[t];
    ull e1 = s_cand[t + 1024];
    for (int k = 2; k <= NCAND; k <<= 1) {
        bool dir0 = ((t & k) == 0);
        bool dir1 = (((t + 1024) & k) == 0);
        for (int j = k >> 1; j > 0; j >>= 1) {
            if (j == 1024) {
                ull lo = umin64(e0, e1), hi = umax64(e0, e1);
                e0 = lo; e1 = hi;
            } else if (j >= 32) {
                s_cand[t] = e0; s_cand[t + 1024] = e1;
                __syncthreads();
                ull f0 = s_cand[t ^ j];
                ull f1 = s_cand[(t ^ j) + 1024];
                bool lower = ((t & j) == 0);
                e0 = (lower == dir0) ? umin64(e0, f0) : umax64(e0, f0);
                e1 = (lower == dir1) ? umin64(e1, f1) : umax64(e1, f1);
                __syncthreads();
            } else {
                ull f0 = __shfl_xor_sync(0xFFFFFFFFu, e0, j);
                ull f1 = __shfl_xor_sync(0xFFFFFFFFu, e1, j);
                bool lower = ((t & j) == 0);
                e0 = (lower == dir0) ? umin64(e0, f0) : umax64(e0, f0);
                e1 = (lower == dir1) ? umin64(e1, f1) : umax64(e1, f1);
            }
        }
    }

    // ---- gather top-1024 (thread t holds sorted element t in e0) ----
    unsigned idx  = (unsigned)(e0 & 0xFFFFFFFFu);
    unsigned mono = ~((unsigned)(e0 >> 32));
    unsigned sbits = (mono & 0x80000000u) ? (mono & 0x7FFFFFFFu) : ~mono;
    float sc = __uint_as_float(sbits);

    const float* pb = pred + (size_t)b * N_PRED * 16;
    const float4* p4 = (const float4*)(pb + (size_t)idx * 16);
    float4 v0 = p4[0];
    float4 v1 = p4[1];
    float4 v2 = p4[2];
    float4 v3 = p4[3];

    float hw = __fmul_rn(v0.z, 0.5f), hh = __fmul_rn(v0.w, 0.5f);
    float x1 = __fsub_rn(v0.x, hw), y1 = __fsub_rn(v0.y, hh);
    float x2 = __fadd_rn(v0.x, hw), y2 = __fadd_rn(v0.y, hh);

    float4* o4 = (float4*)(dout + (((size_t)(b * KTOP)) + t) * 16);
    o4[0] = make_float4(x1, y1, x2, y2);
    o4[1] = make_float4(sc, v1.y, v1.z, v1.w);
    o4[2] = v2;
    o4[3] = make_float4(v3.x, v3.y, v3.z, 0.0f);

    g_boxes[b * KTOP + t] = make_float4(x1, y1, x2, y2);
    g_topsc[b * KTOP + t] = sc;
}

// ================= K3: suppression pairs, triangle-packed, FFMA screen =================
__global__ void __launch_bounds__(1024)
k3_mask() {
    __shared__ float4 sbox[KTOP];
    __shared__ float  staj[KTOP];   // 0.45 * area * (1 - 1e-5)
    int b = blockIdx.y;
    int t = threadIdx.x;

    float4 bx = g_boxes[b * KTOP + t];
    sbox[t] = bx;
    float area = __fmul_rn(__fsub_rn(bx.z, bx.x), __fsub_rn(bx.w, bx.y));
    staj[t] = 0.45f * area * 0.99999f;
    __syncthreads();

    int g = blockIdx.x * 32 + (t >> 5);
    if (g >= NTRI) return;

    // map g -> (rowblock r, wordblock w>=r)
    int u = NTRI - g;
    int n = (int)((__fsqrt_rn((float)(8 * u + 1)) - 1.0f) * 0.5f);
    while (n * (n + 1) / 2 < u) n++;
    while ((n - 1) * n / 2 >= u) n--;
    int r    = 32 - n;
    int base = NTRI - n * (n + 1) / 2;
    int w    = r + (g - base);

    int lane = t & 31;
    int i = r * 32 + lane;
    float4 bi = sbox[i];
    float  ai = __fmul_rn(__fsub_rn(bi.z, bi.x), __fsub_rn(bi.w, bi.y));
    float  tqi_lo = 0.45f * (__fadd_rn(ai, 1e-7f)) * 0.99999f;

    unsigned amb = 0;
    #pragma unroll
    for (int kk = 0; kk < 32; kk++) {
        int j = w * 32 + kk;
        float4 bj = sbox[j];
        float iw = fmaxf(__fsub_rn(fminf(bi.z, bj.z), fmaxf(bi.x, bj.x)), 0.0f);
        float ih = fmaxf(__fsub_rn(fminf(bi.w, bj.w), fmaxf(bi.y, bj.y)), 0.0f);
        float inter = __fmul_rn(iw, ih);
        // screen: 1.45*inter > 0.45*(ai+aj+eps), RHS shrunk by 1e-5 (superset of true cond)
        if (fmaf(inter, 1.45f, -tqi_lo) > staj[j]) amb |= 1u << kk;
    }
    if (w == r) amb &= (0xFFFFFFFEu << lane);   // strict upper triangle on diagonal

    // exact resolution (bit-exact vs reference's RN divide)
    unsigned sup = 0;
    while (amb) {
        int kk = __ffs(amb) - 1; amb &= amb - 1;
        int j = w * 32 + kk;
        float4 bj = sbox[j];
        float aj = __fmul_rn(__fsub_rn(bj.z, bj.x), __fsub_rn(bj.w, bj.y));
        float iw = fmaxf(__fsub_rn(fminf(bi.z, bj.z), fmaxf(bi.x, bj.x)), 0.0f);
        float ih = fmaxf(__fsub_rn(fminf(bi.w, bj.w), fmaxf(bi.y, bj.y)), 0.0f);
        float inter = __fmul_rn(iw, ih);
        float den = __fadd_rn(__fsub_rn(__fadd_rn(ai, aj), inter), 1e-7f);
        if (__fdiv_rn(inter, den) > IOU_T) sup |= 1u << kk;
    }

    // emit sparse pairs (i suppresses j), j = w*32 + bit; all pairs have i < j
    int npairs = __popc(sup);
    if (npairs) {
        unsigned pos = atomicAdd(&g_paircnt[b], (unsigned)npairs);
        while (sup) {
            int kk = __ffs(sup) - 1; sup &= sup - 1;
            if (pos < PAIR_CAP)
                g_pairs[b * PAIR_CAP + pos] = ((unsigned)i << 16) | (unsigned)(w * 32 + kk);
            pos++;
        }
    }
}

// ================= K4: parallel Jacobi fixpoint on smem-staged pairs + output =================
// keep[j] = valid[j] & ~OR_{(i,j) in P} keep[i]   (all pairs i<j)
// Unique fixpoint == sequential greedy result; converges in <= depth+1 iterations.
__global__ void __launch_bounds__(512)
k4_reduce(float* __restrict__ dout, float* __restrict__ keepout, int writeKeep) {
    __shared__ unsigned s_pairs[SMEM_PAIRS];   // 24 KB
    __shared__ unsigned s_valid[32], s_keep[32], s_removed[32];
    __shared__ unsigned s_pcnt;
    __shared__ int s_changed;

    int b   = blockIdx.x;
    int tid = threadIdx.x;      // 0..511

    // ---- vmask ballots ----
    #pragma unroll
    for (int it = 0; it < 2; it++) {
        int row = it * 512 + tid;
        float scv = g_topsc[b * KTOP + row];
        unsigned bal = __ballot_sync(0xFFFFFFFFu, scv > 0.0f);
        if ((tid & 31) == 0) s_valid[row >> 5] = bal;
    }

    // ---- re-zero per-image counters for the NEXT kernel_launch call ----
    {
        uint4* hz = (uint4*)&g_hist[b * NBINS];   // 1024 uint4
        hz[tid]       = make_uint4(0, 0, 0, 0);
        hz[tid + 512] = make_uint4(0, 0, 0, 0);
    }
    // tid 0 alone reads-then-zeros g_paircnt (program-ordered within one thread)
    if (tid == 0) {
        unsigned pc = g_paircnt[b];
        g_paircnt[b] = 0;
        s_pcnt = pc;
    }
    __syncthreads();
    unsigned pcnt = s_pcnt;
    if (pcnt > PAIR_CAP) pcnt = PAIR_CAP;

    // ---- stage pair list into smem (one pass, high MLP) ----
    const unsigned* pl = &g_pairs[b * PAIR_CAP];
    unsigned pstage = (pcnt < SMEM_PAIRS) ? pcnt : SMEM_PAIRS;
    for (unsigned p = tid; p < pstage; p += 512)
        s_pairs[p] = pl[p];

    if (tid < 32) s_keep[tid] = s_valid[tid];
    __syncthreads();

    for (;;) {
        if (tid < 32) s_removed[tid] = 0u;
        if (tid == 0) s_changed = 0;
        __syncthreads();

        for (unsigned p = tid; p < pcnt; p += 512) {
            unsigned pr = (p < SMEM_PAIRS) ? s_pairs[p] : pl[p];
            unsigned i = pr >> 16;
            unsigned j = pr & 0xFFFFu;
            if ((s_keep[i >> 5] >> (i & 31)) & 1u)
                atomicOr(&s_removed[j >> 5], 1u << (j & 31));
        }
        __syncthreads();

        if (tid < 32) {
            unsigned nk = s_valid[tid] & ~s_removed[tid];
            if (nk != s_keep[tid]) { s_keep[tid] = nk; s_changed = 1; }
        }
        __syncthreads();
        int ch = s_changed;        // snapshot BEFORE anyone can overwrite it
        __syncthreads();           // all reads complete before next iter's writes
        if (!ch) break;
    }

    // ---- masked output: 512 threads x 2 rows ----
    #pragma unroll
    for (int it = 0; it < 2; it++) {
        int row = it * 512 + tid;
        unsigned keepbit = (s_keep[row >> 5] >> (row & 31)) & 1u;
        float* o = dout + ((size_t)b * KTOP + row) * 16;
        if (!keepbit) {
            float4 z = make_float4(0.f, 0.f, 0.f, 0.f);
            ((float4*)o)[0] = z; ((float4*)o)[1] = z;
            ((float4*)o)[2] = z; ((float4*)o)[3] = z;
        }
        if (writeKeep) keepout[b * KTOP + row] = keepbit ? 1.0f : 0.0f;
    }
}

// ---------------- launch ----------------
extern "C" void kernel_launch(void* const* d_in, const int* in_sizes, int n_in,
                              void* d_out, int out_size) {
    const float* pred = (const float*)d_in[0];
    float* out = (float*)d_out;
    const int DET = B_IMG * KTOP * 16;
    int writeKeep = (out_size >= DET + B_IMG * KTOP) ? 1 : 0;
    float* keepout = out + DET;

    k1_score<<<dim3(25, B_IMG), 1024>>>(pred);
    k2_topk<<<B_IMG, 1024>>>(pred, out);
    k3_mask<<<dim3(17, B_IMG), 1024>>>();
    k4_reduce<<<B_IMG, 512>>>(out, keepout, writeKeep);
}